// round 11
// baseline (speedup 1.0000x reference)
#include <cuda_runtime.h>
#include <cuda_bf16.h>
#include <cstdint>

// Problem constants (fixed by the reference)
#define NNODES 50000
#define NEDGES 400000
#define CH     256
#define K1     512
#define K2     256

// ---------------------------------------------------------------------------
// Scratch (__device__ globals; no allocations)
// ---------------------------------------------------------------------------
__device__ float    g_h1[(size_t)NNODES * CH];      // GEMM1 out
__device__ float    g_h2[(size_t)NNODES * CH];      // GEMM2 out
__device__ float    g_dinv[NNODES];
__device__ int      g_ideg[NNODES];
__device__ int      g_rowptr[NNODES + 1];
__device__ int      g_cursor[NNODES];
__device__ int      g_esrc[NEDGES];
__device__ int      g_is64;

// bf16 hi/lo pre-converted operands (u32 = packed bf16x2)
__device__ uint32_t g_hrhi[(size_t)NNODES * K2 / 2];
__device__ uint32_t g_hrlo[(size_t)NNODES * K2 / 2];
__device__ uint32_t g_w1hi[CH * K1 / 2];
__device__ uint32_t g_w1lo[CH * K1 / 2];
__device__ uint32_t g_w2hi[CH * K2 / 2];
__device__ uint32_t g_w2lo[CH * K2 / 2];

// ---------------------------------------------------------------------------
// Helpers
// ---------------------------------------------------------------------------
__device__ __forceinline__ uint32_t smem_u32(const void* p) {
    uint32_t a;
    asm("{ .reg .u64 t; cvta.to.shared.u64 t, %1; cvt.u32.u64 %0, t; }" : "=r"(a) : "l"(p));
    return a;
}

#define SW128(o) ((o) ^ (((o) >> 3) & 0x70))

__device__ __forceinline__ void ldsm4(uint32_t* r, uint32_t addr) {
    asm volatile("ldmatrix.sync.aligned.m8n8.x4.shared.b16 {%0,%1,%2,%3}, [%4];"
                 : "=r"(r[0]), "=r"(r[1]), "=r"(r[2]), "=r"(r[3]) : "r"(addr));
}

__device__ __forceinline__ void mma16816(float* c, const uint32_t* a,
                                         uint32_t b0, uint32_t b1) {
    asm volatile(
        "mma.sync.aligned.m16n8k16.row.col.f32.bf16.bf16.f32 "
        "{%0,%1,%2,%3}, {%4,%5,%6,%7}, {%8,%9}, {%0,%1,%2,%3};"
        : "+f"(c[0]), "+f"(c[1]), "+f"(c[2]), "+f"(c[3])
        : "r"(a[0]), "r"(a[1]), "r"(a[2]), "r"(a[3]), "r"(b0), "r"(b1));
}

__device__ __forceinline__ void cpa16(uint32_t dst, const void* src, uint32_t srcsz) {
    asm volatile("cp.async.cg.shared.global [%0], [%1], 16, %2;"
                 :: "r"(dst), "l"(src), "r"(srcsz) : "memory");
}
#define CPA_COMMIT() asm volatile("cp.async.commit_group;" ::: "memory")
#define CPA_WAIT(N)  asm volatile("cp.async.wait_group %0;" :: "n"(N) : "memory")

// Split two fp32 into bf16x2 hi-word + residual bf16x2 lo-word
__device__ __forceinline__ void bsplit2(float x0, float x1, uint32_t& hi, uint32_t& lo) {
    __nv_bfloat16 h0 = __float2bfloat16_rn(x0);
    __nv_bfloat16 h1 = __float2bfloat16_rn(x1);
    float r0 = x0 - __bfloat162float(h0);
    float r1 = x1 - __bfloat162float(h1);
    __nv_bfloat162 hp, lp;
    hp.x = h0; hp.y = h1;
    lp.x = __float2bfloat16_rn(r0); lp.y = __float2bfloat16_rn(r1);
    hi = *reinterpret_cast<uint32_t*>(&hp);
    lo = *reinterpret_cast<uint32_t*>(&lp);
}

// ---------------------------------------------------------------------------
// Weight conversion: fp32 -> bf16 hi/lo, 8 floats per thread, W1+W2 in one grid
// ---------------------------------------------------------------------------
#define W1_N8 (CH * K1 / 8)     // 16384
#define W2_N8 (CH * K2 / 8)     // 8192
__global__ void k_conv_w(const float* __restrict__ w1, const float* __restrict__ w2)
{
    int idx = blockIdx.x * blockDim.x + threadIdx.x;
    const float* in;
    uint32_t *hi, *lo;
    int li;
    if (idx < W1_N8)      { in = w1; hi = g_w1hi; lo = g_w1lo; li = idx; }
    else if (idx < W1_N8 + W2_N8) { in = w2; hi = g_w2hi; lo = g_w2lo; li = idx - W1_N8; }
    else return;
    const float* p = in + (size_t)li * 8;
    float4 a = *(const float4*)p;
    float4 b = *(const float4*)(p + 4);
    uint32_t h0, l0, h1, l1, h2, l2, h3, l3;
    bsplit2(a.x, a.y, h0, l0);  bsplit2(a.z, a.w, h1, l1);
    bsplit2(b.x, b.y, h2, l2);  bsplit2(b.z, b.w, h3, l3);
    *(uint4*)&hi[(size_t)li * 4] = make_uint4(h0, h1, h2, h3);
    *(uint4*)&lo[(size_t)li * 4] = make_uint4(l0, l1, l2, l3);
}

// ---------------------------------------------------------------------------
// bf16 split-3 GEMM, cp.async 3-stage pipeline, full-width N=256 tile.
// C[M,256] = A[M,K] @ B[256,K]^T. CTA tile 128x256, BK=32, 512 threads.
// Row layout (128B, SW128): [hi: 32 bf16 = 64B | lo: 32 bf16 = 64B]
// Stage = A(16KB) + B(32KB) = 48KB; 3 stages = 144KB. 16 warps: 4m x 4n.
// F32A variant: A read as raw fp32 (LDG.128), split in-register, STS'd after
// the MMA phase (LDG latency hidden under tensor work). B always cp.async.
// ---------------------------------------------------------------------------
#define GEMM_NTH   512
#define STAGE_SZ   49152
#define GEMM_SMEM  (3 * STAGE_SZ)

// B tile: 256 rows x 8 groups = 2048 items, 4 per thread (cp.async)
__device__ __forceinline__ void load_b(
    const uint32_t* __restrict__ Bhi, const uint32_t* __restrict__ Blo,
    uint32_t bufB, int K, int k0, int t)
{
#pragma unroll
    for (int it = 0; it < 4; it++) {
        int g = t + it * GEMM_NTH;
        int r = g >> 3, j = g & 7;
        const uint32_t* src = (j < 4) ? Bhi : Blo;
        int koff = (j & 3) * 8;
        const void* p = &src[((size_t)r * K + k0 + koff) >> 1];
        cpa16(bufB + SW128((uint32_t)(r * 128 + j * 16)), p, 16u);
    }
}

// A tile pre-split: 128 rows x 8 groups = 1024 items, 2 per thread (cp.async)
__device__ __forceinline__ void load_a_split(
    const uint32_t* __restrict__ Ahi, const uint32_t* __restrict__ Alo,
    uint32_t bufA, int brow, int M, int K, int k0, int t)
{
#pragma unroll
    for (int it = 0; it < 2; it++) {
        int g = t + it * GEMM_NTH;
        int r = g >> 3, j = g & 7;
        int gr = brow + r;
        const uint32_t* src = (j < 4) ? Ahi : Alo;
        int koff = (j & 3) * 8;
        const void* p = &src[((size_t)gr * K + k0 + koff) >> 1];
        cpa16(bufA + SW128((uint32_t)(r * 128 + j * 16)), p, gr < M ? 16u : 0u);
    }
}

// A tile fp32: LDG into regs (2 float4 per thread; item = 4 k-elems)
__device__ __forceinline__ void lda_f32(
    const float* __restrict__ X, int brow, int M, int K, int k0, int t, float4* v)
{
#pragma unroll
    for (int it = 0; it < 2; it++) {
        int g = t + it * GEMM_NTH;
        int r = g >> 3, j = g & 7;          // j: float4 index within 32 k-elems
        int gr = brow + r;
        v[it] = (gr < M) ? *(const float4*)&X[(size_t)gr * K + k0 + j * 4]
                         : make_float4(0.f, 0.f, 0.f, 0.f);
    }
}

// split regs -> smem stage (8B hi + 8B lo per item)
__device__ __forceinline__ void sta_f32(uint32_t bufA, int t, const float4* v)
{
#pragma unroll
    for (int it = 0; it < 2; it++) {
        int g = t + it * GEMM_NTH;
        int r = g >> 3, j = g & 7;
        uint32_t h0, l0, h1, l1;
        bsplit2(v[it].x, v[it].y, h0, l0);
        bsplit2(v[it].z, v[it].w, h1, l1);
        uint32_t offh = SW128((uint32_t)(r * 128 + j * 8));
        uint32_t offl = SW128((uint32_t)(r * 128 + 64 + j * 8));
        asm volatile("st.shared.v2.b32 [%0], {%1,%2};" :: "r"(bufA + offh), "r"(h0), "r"(h1) : "memory");
        asm volatile("st.shared.v2.b32 [%0], {%1,%2};" :: "r"(bufA + offl), "r"(l0), "r"(l1) : "memory");
    }
}

template <bool F32A>
__device__ __forceinline__ void mma_gemm_body(
    const float* __restrict__ Xf,
    const uint32_t* __restrict__ Ahi, const uint32_t* __restrict__ Alo,
    const uint32_t* __restrict__ Bhi, const uint32_t* __restrict__ Blo,
    float* __restrict__ C, int M, int K)
{
    extern __shared__ char dsm_raw[];
    const uint32_t base = smem_u32(dsm_raw);

    const int t    = threadIdx.x;
    const int wid  = t >> 5;
    const int lane = t & 31;
    const int brow = blockIdx.x * 128;

    const int warp_m = (wid >> 2) * 32;   // 0,32,64,96
    const int warp_n = (wid & 3) * 64;    // 0,64,128,192

    float acc[2][8][4];
#pragma unroll
    for (int i = 0; i < 2; i++)
#pragma unroll
        for (int j = 0; j < 8; j++)
#pragma unroll
            for (int q = 0; q < 4; q++) acc[i][j][q] = 0.0f;

    const int lr = lane & 15;
    const int kh = lane >> 4;

    const int nch = K >> 5;

    // prologue: chunks 0,1
    if (F32A) {
        float4 v[2];
        lda_f32(Xf, brow, M, K, 0, t, v);  sta_f32(base, t, v);
        load_b(Bhi, Blo, base + 16384, K, 0, t);
        CPA_COMMIT();
        lda_f32(Xf, brow, M, K, 32, t, v); sta_f32(base + STAGE_SZ, t, v);
        load_b(Bhi, Blo, base + STAGE_SZ + 16384, K, 32, t);
        CPA_COMMIT();
    } else {
        load_a_split(Ahi, Alo, base, brow, M, K, 0, t);
        load_b(Bhi, Blo, base + 16384, K, 0, t);
        CPA_COMMIT();
        load_a_split(Ahi, Alo, base + STAGE_SZ, brow, M, K, 32, t);
        load_b(Bhi, Blo, base + STAGE_SZ + 16384, K, 32, t);
        CPA_COMMIT();
    }

    for (int c = 0; c < nch; c++) {
        float4 av[2];
        const bool pre = (c + 2 < nch);
        uint32_t nxt = base + ((c + 2) % 3) * STAGE_SZ;
        if (pre) {
            if (F32A) {
                lda_f32(Xf, brow, M, K, (c + 2) << 5, t, av);   // LDG in flight
            } else {
                load_a_split(Ahi, Alo, nxt, brow, M, K, (c + 2) << 5, t);
            }
            load_b(Bhi, Blo, nxt + 16384, K, (c + 2) << 5, t);
            CPA_COMMIT();
            CPA_WAIT(2);
        } else if (c + 1 < nch) {
            CPA_WAIT(1);
        } else {
            CPA_WAIT(0);
        }
        __syncthreads();

        const uint32_t cur  = base + (c % 3) * STAGE_SZ;
        const uint32_t curA = cur;
        const uint32_t curB = cur + 16384;

#pragma unroll
        for (int s = 0; s < 2; s++) {
            const int jh = s * 2 + kh;     // hi groups 0..3
            const int jl = jh + 4;         // lo groups 4..7

            uint32_t ah[2][4], bh[4][4];
#pragma unroll
            for (int mi = 0; mi < 2; mi++) {
                int r = warp_m + mi * 16 + lr;
                ldsm4(ah[mi], curA + (uint32_t)(r * 128 + ((jh ^ (r & 7)) << 4)));
            }
#pragma unroll
            for (int nj = 0; nj < 4; nj++) {
                int r = warp_n + nj * 16 + lr;
                ldsm4(bh[nj], curB + (uint32_t)(r * 128 + ((jh ^ (r & 7)) << 4)));
            }
            // hi*hi
#pragma unroll
            for (int mi = 0; mi < 2; mi++)
#pragma unroll
                for (int nj = 0; nj < 4; nj++) {
                    mma16816(acc[mi][nj * 2 + 0], ah[mi], bh[nj][0], bh[nj][2]);
                    mma16816(acc[mi][nj * 2 + 1], ah[mi], bh[nj][1], bh[nj][3]);
                }
            // lo*hi
            {
                uint32_t al[2][4];
#pragma unroll
                for (int mi = 0; mi < 2; mi++) {
                    int r = warp_m + mi * 16 + lr;
                    ldsm4(al[mi], curA + (uint32_t)(r * 128 + ((jl ^ (r & 7)) << 4)));
                }
#pragma unroll
                for (int mi = 0; mi < 2; mi++)
#pragma unroll
                    for (int nj = 0; nj < 4; nj++) {
                        mma16816(acc[mi][nj * 2 + 0], al[mi], bh[nj][0], bh[nj][2]);
                        mma16816(acc[mi][nj * 2 + 1], al[mi], bh[nj][1], bh[nj][3]);
                    }
            }
            // hi*lo
            {
                uint32_t bl[4][4];
#pragma unroll
                for (int nj = 0; nj < 4; nj++) {
                    int r = warp_n + nj * 16 + lr;
                    ldsm4(bl[nj], curB + (uint32_t)(r * 128 + ((jl ^ (r & 7)) << 4)));
                }
#pragma unroll
                for (int mi = 0; mi < 2; mi++)
#pragma unroll
                    for (int nj = 0; nj < 4; nj++) {
                        mma16816(acc[mi][nj * 2 + 0], ah[mi], bl[nj][0], bl[nj][2]);
                        mma16816(acc[mi][nj * 2 + 1], ah[mi], bl[nj][1], bl[nj][3]);
                    }
            }
        }

        // F32A: LDG data has arrived under the MMA phase; write it to the
        // (c+2)%3 stage. Safe: its last readers finished at the previous
        // exit-sync; visibility to iter c+2 is ordered by the next syncs.
        if (F32A && pre) sta_f32(nxt, t, av);
        __syncthreads();
    }

    // epilogue
    const int qr = lane >> 2;
    const int qc = (lane & 3) * 2;
#pragma unroll
    for (int mi = 0; mi < 2; mi++) {
        int r0 = brow + warp_m + mi * 16 + qr;
#pragma unroll
        for (int n8 = 0; n8 < 8; n8++) {
            int col = warp_n + n8 * 8 + qc;
            if (r0 < M) {
                float2 v = make_float2(acc[mi][n8][0], acc[mi][n8][1]);
                *(float2*)&C[(size_t)r0 * 256 + col] = v;
            }
            if (r0 + 8 < M) {
                float2 v = make_float2(acc[mi][n8][2], acc[mi][n8][3]);
                *(float2*)&C[(size_t)(r0 + 8) * 256 + col] = v;
            }
        }
    }
}

__global__ void __launch_bounds__(GEMM_NTH, 1)
k_mmagemm1(const float* __restrict__ x) {
    mma_gemm_body<true>(x, nullptr, nullptr, g_w1hi, g_w1lo, g_h1, NNODES, K1);
}
__global__ void __launch_bounds__(GEMM_NTH, 1)
k_mmagemm2() {
    mma_gemm_body<false>(nullptr, g_hrhi, g_hrlo, g_w2hi, g_w2lo, g_h2, NNODES, K2);
}

// ---------------------------------------------------------------------------
// edge_index access (int64 per spec; tolerate int32 via runtime detection)
// ---------------------------------------------------------------------------
__device__ __forceinline__ int edge_idx(const void* ei, int half, int e) {
    if (g_is64) return (int)((const long long*)ei)[(size_t)half * NEDGES + e];
    return ((const int*)ei)[(size_t)half * NEDGES + e];
}

// ---------------------------------------------------------------------------
// CSR build: zero+detect -> count -> scan(+dinv) -> fill
// ---------------------------------------------------------------------------
__global__ void k_zero_detect(const long long* __restrict__ ei) {
    int i = blockIdx.x * blockDim.x + threadIdx.x;
    if (i < NNODES) g_ideg[i] = 0;
    if (blockIdx.x == 0 && threadIdx.x == 0) {
        int is64 = 1;
        for (int q = 0; q < 256; q++) {
            long long v = ei[q];
            if (v < 0 || v >= NNODES) { is64 = 0; break; }
        }
        g_is64 = is64;
    }
}

__global__ void k_count(const void* __restrict__ ei) {
    int e = blockIdx.x * blockDim.x + threadIdx.x;
    if (e < NEDGES) atomicAdd(&g_ideg[edge_idx(ei, 1, e)], 1);
}

#define SCAN_T 1024
#define SCAN_C ((NNODES + SCAN_T - 1) / SCAN_T)
__global__ void __launch_bounds__(SCAN_T)
k_scan() {
    __shared__ int part[SCAN_T];
    const int t = threadIdx.x;
    const int start = t * SCAN_C;
    const int end   = min(start + SCAN_C, NNODES);
    int s = 0;
    for (int i = start; i < end; i++) s += g_ideg[i];
    part[t] = s;
    __syncthreads();
    for (int off = 1; off < SCAN_T; off <<= 1) {
        int v = (t >= off) ? part[t - off] : 0;
        __syncthreads();
        part[t] += v;
        __syncthreads();
    }
    int run = part[t] - s;
    for (int i = start; i < end; i++) {
        int d = g_ideg[i];
        g_rowptr[i] = run;
        g_cursor[i] = run;
        g_dinv[i]   = rsqrtf(1.0f + (float)d);
        run += d;
    }
    if (t == SCAN_T - 1) g_rowptr[NNODES] = part[SCAN_T - 1];
}

__global__ void k_fill(const void* __restrict__ ei) {
    int e = blockIdx.x * blockDim.x + threadIdx.x;
    if (e >= NEDGES) return;
    int s = edge_idx(ei, 0, e);
    int d = edge_idx(ei, 1, e);
    int pos = atomicAdd(&g_cursor[d], 1);
    g_esrc[pos] = s;
}

// ---------------------------------------------------------------------------
// Gather aggregation: one warp per node.
// ---------------------------------------------------------------------------
__device__ __forceinline__ void gather_acc(
    const float* __restrict__ h, const float* __restrict__ bias,
    int node, int lane, float4& a0, float4& a1)
{
    const float dv = g_dinv[node];
    const float* hd = h + (size_t)node * CH;
    a0 = *(const float4*)&hd[lane * 4];
    a1 = *(const float4*)&hd[128 + lane * 4];
    const float sv = dv * dv;
    a0.x *= sv; a0.y *= sv; a0.z *= sv; a0.w *= sv;
    a1.x *= sv; a1.y *= sv; a1.z *= sv; a1.w *= sv;

    const int p0 = g_rowptr[node];
    const int p1 = g_rowptr[node + 1];
    for (int p = p0; p < p1; p++) {
        int s = g_esrc[p];
        float w = g_dinv[s] * dv;
        const float* hs = h + (size_t)s * CH;
        float4 v0 = *(const float4*)&hs[lane * 4];
        float4 v1 = *(const float4*)&hs[128 + lane * 4];
        a0.x = fmaf(v0.x, w, a0.x); a0.y = fmaf(v0.y, w, a0.y);
        a0.z = fmaf(v0.z, w, a0.z); a0.w = fmaf(v0.w, w, a0.w);
        a1.x = fmaf(v1.x, w, a1.x); a1.y = fmaf(v1.y, w, a1.y);
        a1.z = fmaf(v1.z, w, a1.z); a1.w = fmaf(v1.w, w, a1.w);
    }

    const float4 b0 = *(const float4*)&bias[lane * 4];
    const float4 b1 = *(const float4*)&bias[128 + lane * 4];
    a0.x += b0.x; a0.y += b0.y; a0.z += b0.z; a0.w += b0.w;
    a1.x += b1.x; a1.y += b1.y; a1.z += b1.z; a1.w += b1.w;
}

// layer 1: relu then emit bf16 hi/lo split directly (GEMM2 input)
__global__ void __launch_bounds__(256)
k_gather1(const float* __restrict__ b1)
{
    const int wid  = threadIdx.x >> 5;
    const int lane = threadIdx.x & 31;
    const int node = blockIdx.x * 8 + wid;
    if (node >= NNODES) return;
    float4 a0, a1;
    gather_acc(g_h1, b1, node, lane, a0, a1);
    a0.x = fmaxf(a0.x, 0.f); a0.y = fmaxf(a0.y, 0.f);
    a0.z = fmaxf(a0.z, 0.f); a0.w = fmaxf(a0.w, 0.f);
    a1.x = fmaxf(a1.x, 0.f); a1.y = fmaxf(a1.y, 0.f);
    a1.z = fmaxf(a1.z, 0.f); a1.w = fmaxf(a1.w, 0.f);

    uint32_t h0, l0, h1, l1;
    size_t bix = (size_t)node * 128 + lane * 2;
    bsplit2(a0.x, a0.y, h0, l0); bsplit2(a0.z, a0.w, h1, l1);
    *(uint2*)&g_hrhi[bix] = make_uint2(h0, h1);
    *(uint2*)&g_hrlo[bix] = make_uint2(l0, l1);
    bsplit2(a1.x, a1.y, h0, l0); bsplit2(a1.z, a1.w, h1, l1);
    *(uint2*)&g_hrhi[bix + 64] = make_uint2(h0, h1);
    *(uint2*)&g_hrlo[bix + 64] = make_uint2(l0, l1);
}

// layer 2: plain output
__global__ void __launch_bounds__(256)
k_gather2(const float* __restrict__ b2, float* __restrict__ out)
{
    const int wid  = threadIdx.x >> 5;
    const int lane = threadIdx.x & 31;
    const int node = blockIdx.x * 8 + wid;
    if (node >= NNODES) return;
    float4 a0, a1;
    gather_acc(g_h2, b2, node, lane, a0, a1);
    float* od = out + (size_t)node * CH;
    *(float4*)&od[lane * 4]       = a0;
    *(float4*)&od[128 + lane * 4] = a1;
}

// ---------------------------------------------------------------------------
// Launch
// ---------------------------------------------------------------------------
extern "C" void kernel_launch(void* const* d_in, const int* in_sizes, int n_in,
                              void* d_out, int out_size)
{
    const float* x   = (const float*)d_in[0];
    const void*  ei  = d_in[1];
    const float* W1  = (const float*)d_in[2];
    const float* b1  = (const float*)d_in[3];
    const float* W2  = (const float*)d_in[4];
    const float* b2  = (const float*)d_in[5];
    float*       out = (float*)d_out;

    static cudaStream_t s2 = nullptr;
    static cudaEvent_t  e0 = nullptr, e1 = nullptr;
    if (!s2) {
        cudaFuncSetAttribute(k_mmagemm1, cudaFuncAttributeMaxDynamicSharedMemorySize, GEMM_SMEM);
        cudaFuncSetAttribute(k_mmagemm2, cudaFuncAttributeMaxDynamicSharedMemorySize, GEMM_SMEM);
        cudaStreamCreateWithFlags(&s2, cudaStreamNonBlocking);
        cudaEventCreateWithFlags(&e0, cudaEventDisableTiming);
        cudaEventCreateWithFlags(&e1, cudaEventDisableTiming);
    }

    const int NTH = 256;
    const int nblk_nodes  = (NNODES + NTH - 1) / NTH;
    const int nblk_edges  = (NEDGES + NTH - 1) / NTH;
    const int nblk_gather = (NNODES + 7) / 8;
    const int nblk_convw  = (W1_N8 + W2_N8 + NTH - 1) / NTH;

    const int gemm_grid = (NNODES + 127) / 128;   // 391

    // fork: CSR chain on s2 (only gather1 depends on it)
    cudaEventRecord(e0, 0);
    cudaStreamWaitEvent(s2, e0, 0);
    k_zero_detect<<<nblk_nodes, NTH, 0, s2>>>((const long long*)ei);
    k_count<<<nblk_edges, NTH, 0, s2>>>(ei);
    k_scan<<<1, SCAN_T, 0, s2>>>();
    k_fill<<<nblk_edges, NTH, 0, s2>>>(ei);
    cudaEventRecord(e1, s2);

    // main: weight conversion + GEMM1 (reads x directly; no conv_x)
    k_conv_w<<<nblk_convw, NTH>>>(W1, W2);
    k_mmagemm1<<<gemm_grid, GEMM_NTH, GEMM_SMEM>>>(x);

    // join: gather1 needs CSR + dinv
    cudaStreamWaitEvent(0, e1, 0);
    k_gather1<<<nblk_gather, NTH>>>(b1);

    // layer 2
    k_mmagemm2<<<gemm_grid, GEMM_NTH, GEMM_SMEM>>>();
    k_gather2<<<nblk_gather, NTH>>>(b2, out);
}

// round 13
// speedup vs baseline: 1.1616x; 1.1616x over previous
#include <cuda_runtime.h>
#include <cuda_bf16.h>
#include <cstdint>

// Problem constants (fixed by the reference)
#define NNODES 50000
#define NEDGES 400000
#define CH     256
#define K1     512
#define K2     256

// ---------------------------------------------------------------------------
// Scratch (__device__ globals; no allocations)
// ---------------------------------------------------------------------------
__device__ float    g_h1[(size_t)NNODES * CH];      // GEMM1 out
__device__ float    g_h2[(size_t)NNODES * CH];      // GEMM2 out
__device__ float    g_dinv[NNODES];
__device__ int      g_ideg[NNODES];
__device__ int      g_rowptr[NNODES + 1];
__device__ int      g_cursor[NNODES];
__device__ int      g_esrc[NEDGES];
__device__ int      g_is64;

// bf16 hi/lo pre-converted operands (u32 = packed bf16x2)
__device__ uint32_t g_xhi[(size_t)NNODES * K1 / 2];
__device__ uint32_t g_xlo[(size_t)NNODES * K1 / 2];
__device__ uint32_t g_hrhi[(size_t)NNODES * K2 / 2];
__device__ uint32_t g_hrlo[(size_t)NNODES * K2 / 2];
__device__ uint32_t g_w1hi[CH * K1 / 2];
__device__ uint32_t g_w1lo[CH * K1 / 2];
__device__ uint32_t g_w2hi[CH * K2 / 2];
__device__ uint32_t g_w2lo[CH * K2 / 2];

// ---------------------------------------------------------------------------
// Helpers
// ---------------------------------------------------------------------------
__device__ __forceinline__ uint32_t smem_u32(const void* p) {
    uint32_t a;
    asm("{ .reg .u64 t; cvta.to.shared.u64 t, %1; cvt.u32.u64 %0, t; }" : "=r"(a) : "l"(p));
    return a;
}

#define SW128(o) ((o) ^ (((o) >> 3) & 0x70))

__device__ __forceinline__ void ldsm4(uint32_t* r, uint32_t addr) {
    asm volatile("ldmatrix.sync.aligned.m8n8.x4.shared.b16 {%0,%1,%2,%3}, [%4];"
                 : "=r"(r[0]), "=r"(r[1]), "=r"(r[2]), "=r"(r[3]) : "r"(addr));
}

__device__ __forceinline__ void mma16816(float* c, const uint32_t* a,
                                         uint32_t b0, uint32_t b1) {
    asm volatile(
        "mma.sync.aligned.m16n8k16.row.col.f32.bf16.bf16.f32 "
        "{%0,%1,%2,%3}, {%4,%5,%6,%7}, {%8,%9}, {%0,%1,%2,%3};"
        : "+f"(c[0]), "+f"(c[1]), "+f"(c[2]), "+f"(c[3])
        : "r"(a[0]), "r"(a[1]), "r"(a[2]), "r"(a[3]), "r"(b0), "r"(b1));
}

__device__ __forceinline__ void cpa16(uint32_t dst, const void* src, uint32_t srcsz) {
    asm volatile("cp.async.cg.shared.global [%0], [%1], 16, %2;"
                 :: "r"(dst), "l"(src), "r"(srcsz) : "memory");
}
#define CPA_COMMIT() asm volatile("cp.async.commit_group;" ::: "memory")
#define CPA_WAIT(N)  asm volatile("cp.async.wait_group %0;" :: "n"(N) : "memory")

// Split two fp32 into bf16x2 hi-word + residual bf16x2 lo-word
__device__ __forceinline__ void bsplit2(float x0, float x1, uint32_t& hi, uint32_t& lo) {
    __nv_bfloat16 h0 = __float2bfloat16_rn(x0);
    __nv_bfloat16 h1 = __float2bfloat16_rn(x1);
    float r0 = x0 - __bfloat162float(h0);
    float r1 = x1 - __bfloat162float(h1);
    __nv_bfloat162 hp, lp;
    hp.x = h0; hp.y = h1;
    lp.x = __float2bfloat16_rn(r0); lp.y = __float2bfloat16_rn(r1);
    hi = *reinterpret_cast<uint32_t*>(&hp);
    lo = *reinterpret_cast<uint32_t*>(&lp);
}

// ---------------------------------------------------------------------------
// Combined conversion kernel: x | W1 | W2 -> bf16 hi/lo, 8 floats per item
// ---------------------------------------------------------------------------
#define X_N8  (NNODES * K1 / 8)    // 3,200,000
#define W1_N8 (CH * K1 / 8)        // 16,384
#define W2_N8 (CH * K2 / 8)        // 8,192
#define CONV_TOTAL (X_N8 + W1_N8 + W2_N8)

__global__ void k_conv_all(const float* __restrict__ x,
                           const float* __restrict__ w1,
                           const float* __restrict__ w2)
{
    int idx = blockIdx.x * blockDim.x + threadIdx.x;
    const float* in;
    uint32_t *hi, *lo;
    int li;
    if (idx < X_N8)                    { in = x;  hi = g_xhi;  lo = g_xlo;  li = idx; }
    else if (idx < X_N8 + W1_N8)       { in = w1; hi = g_w1hi; lo = g_w1lo; li = idx - X_N8; }
    else if (idx < CONV_TOTAL)         { in = w2; hi = g_w2hi; lo = g_w2lo; li = idx - X_N8 - W1_N8; }
    else return;
    const float* p = in + (size_t)li * 8;
    float4 a = *(const float4*)p;
    float4 b = *(const float4*)(p + 4);
    uint32_t h0, l0, h1, l1, h2, l2, h3, l3;
    bsplit2(a.x, a.y, h0, l0);  bsplit2(a.z, a.w, h1, l1);
    bsplit2(b.x, b.y, h2, l2);  bsplit2(b.z, b.w, h3, l3);
    *(uint4*)&hi[(size_t)li * 4] = make_uint4(h0, h1, h2, h3);
    *(uint4*)&lo[(size_t)li * 4] = make_uint4(l0, l1, l2, l3);
}

// ---------------------------------------------------------------------------
// bf16 split-3 GEMM, cp.async 3-stage pipeline, full-width N=256 tile.
// C[M,256] = A[M,K] @ B[256,K]^T. CTA tile 128x256, BK=32, 512 threads.
// Row layout (128B, SW128): [hi: 32 bf16 = 64B | lo: 32 bf16 = 64B]
// Stage = A(16KB) + B(32KB) = 48KB; 3 stages = 144KB. 16 warps: 4m x 4n.
// ---------------------------------------------------------------------------
#define GEMM_NTH   512
#define STAGE_SZ   49152
#define GEMM_SMEM  (3 * STAGE_SZ)

__device__ __forceinline__ void load_chunk(
    const uint32_t* __restrict__ Ahi, const uint32_t* __restrict__ Alo,
    const uint32_t* __restrict__ Bhi, const uint32_t* __restrict__ Blo,
    uint32_t buf, int brow, int M, int K, int k0, int t)
{
    const uint32_t bufA = buf;
    const uint32_t bufB = buf + 16384;
    // A: 128 rows x 8 groups = 1024 items, 2 per thread
#pragma unroll
    for (int it = 0; it < 2; it++) {
        int g = t + it * GEMM_NTH;
        int r = g >> 3, j = g & 7;
        int gr = brow + r;
        const uint32_t* src = (j < 4) ? Ahi : Alo;
        int koff = (j & 3) * 8;
        const void* p = &src[((size_t)gr * K + k0 + koff) >> 1];
        cpa16(bufA + SW128((uint32_t)(r * 128 + j * 16)), p, gr < M ? 16u : 0u);
    }
    // B: 256 rows x 8 groups = 2048 items, 4 per thread
#pragma unroll
    for (int it = 0; it < 4; it++) {
        int g = t + it * GEMM_NTH;
        int r = g >> 3, j = g & 7;
        const uint32_t* src = (j < 4) ? Bhi : Blo;
        int koff = (j & 3) * 8;
        const void* p = &src[((size_t)r * K + k0 + koff) >> 1];
        cpa16(bufB + SW128((uint32_t)(r * 128 + j * 16)), p, 16u);
    }
}

__device__ __forceinline__ void mma_gemm_body(
    const uint32_t* __restrict__ Ahi, const uint32_t* __restrict__ Alo,
    const uint32_t* __restrict__ Bhi, const uint32_t* __restrict__ Blo,
    float* __restrict__ C, int M, int K)
{
    extern __shared__ char dsm_raw[];
    const uint32_t base = smem_u32(dsm_raw);

    const int t    = threadIdx.x;
    const int wid  = t >> 5;
    const int lane = t & 31;
    const int brow = blockIdx.x * 128;

    const int warp_m = (wid >> 2) * 32;   // 0,32,64,96
    const int warp_n = (wid & 3) * 64;    // 0,64,128,192

    float acc[2][8][4];
#pragma unroll
    for (int i = 0; i < 2; i++)
#pragma unroll
        for (int j = 0; j < 8; j++)
#pragma unroll
            for (int q = 0; q < 4; q++) acc[i][j][q] = 0.0f;

    const int lr = lane & 15;
    const int kh = lane >> 4;

    const int nch = K >> 5;

    // prologue: chunks 0,1
    load_chunk(Ahi, Alo, Bhi, Blo, base, brow, M, K, 0, t);
    CPA_COMMIT();
    load_chunk(Ahi, Alo, Bhi, Blo, base + STAGE_SZ, brow, M, K, 32, t);
    CPA_COMMIT();

    for (int c = 0; c < nch; c++) {
        if (c + 2 < nch) {
            uint32_t nxt = base + ((c + 2) % 3) * STAGE_SZ;
            load_chunk(Ahi, Alo, Bhi, Blo, nxt, brow, M, K, (c + 2) << 5, t);
            CPA_COMMIT();
            CPA_WAIT(2);
        } else if (c + 1 < nch) {
            CPA_WAIT(1);
        } else {
            CPA_WAIT(0);
        }
        __syncthreads();

        const uint32_t cur  = base + (c % 3) * STAGE_SZ;
        const uint32_t curA = cur;
        const uint32_t curB = cur + 16384;

#pragma unroll
        for (int s = 0; s < 2; s++) {
            const int jh = s * 2 + kh;     // hi groups 0..3
            const int jl = jh + 4;         // lo groups 4..7

            uint32_t ah[2][4], bh[4][4];
#pragma unroll
            for (int mi = 0; mi < 2; mi++) {
                int r = warp_m + mi * 16 + lr;
                ldsm4(ah[mi], curA + (uint32_t)(r * 128 + ((jh ^ (r & 7)) << 4)));
            }
#pragma unroll
            for (int nj = 0; nj < 4; nj++) {
                int r = warp_n + nj * 16 + lr;
                ldsm4(bh[nj], curB + (uint32_t)(r * 128 + ((jh ^ (r & 7)) << 4)));
            }
            // hi*hi
#pragma unroll
            for (int mi = 0; mi < 2; mi++)
#pragma unroll
                for (int nj = 0; nj < 4; nj++) {
                    mma16816(acc[mi][nj * 2 + 0], ah[mi], bh[nj][0], bh[nj][2]);
                    mma16816(acc[mi][nj * 2 + 1], ah[mi], bh[nj][1], bh[nj][3]);
                }
            // lo*hi
            {
                uint32_t al[2][4];
#pragma unroll
                for (int mi = 0; mi < 2; mi++) {
                    int r = warp_m + mi * 16 + lr;
                    ldsm4(al[mi], curA + (uint32_t)(r * 128 + ((jl ^ (r & 7)) << 4)));
                }
#pragma unroll
                for (int mi = 0; mi < 2; mi++)
#pragma unroll
                    for (int nj = 0; nj < 4; nj++) {
                        mma16816(acc[mi][nj * 2 + 0], al[mi], bh[nj][0], bh[nj][2]);
                        mma16816(acc[mi][nj * 2 + 1], al[mi], bh[nj][1], bh[nj][3]);
                    }
            }
            // hi*lo
            {
                uint32_t bl[4][4];
#pragma unroll
                for (int nj = 0; nj < 4; nj++) {
                    int r = warp_n + nj * 16 + lr;
                    ldsm4(bl[nj], curB + (uint32_t)(r * 128 + ((jl ^ (r & 7)) << 4)));
                }
#pragma unroll
                for (int mi = 0; mi < 2; mi++)
#pragma unroll
                    for (int nj = 0; nj < 4; nj++) {
                        mma16816(acc[mi][nj * 2 + 0], ah[mi], bl[nj][0], bl[nj][2]);
                        mma16816(acc[mi][nj * 2 + 1], ah[mi], bl[nj][1], bl[nj][3]);
                    }
            }
        }
        __syncthreads();
    }

    // epilogue
    const int qr = lane >> 2;
    const int qc = (lane & 3) * 2;
#pragma unroll
    for (int mi = 0; mi < 2; mi++) {
        int r0 = brow + warp_m + mi * 16 + qr;
#pragma unroll
        for (int n8 = 0; n8 < 8; n8++) {
            int col = warp_n + n8 * 8 + qc;
            if (r0 < M) {
                float2 v = make_float2(acc[mi][n8][0], acc[mi][n8][1]);
                *(float2*)&C[(size_t)r0 * 256 + col] = v;
            }
            if (r0 + 8 < M) {
                float2 v = make_float2(acc[mi][n8][2], acc[mi][n8][3]);
                *(float2*)&C[(size_t)(r0 + 8) * 256 + col] = v;
            }
        }
    }
}

__global__ void __launch_bounds__(GEMM_NTH, 1)
k_mmagemm1() { mma_gemm_body(g_xhi, g_xlo, g_w1hi, g_w1lo, g_h1, NNODES, K1); }
__global__ void __launch_bounds__(GEMM_NTH, 1)
k_mmagemm2() { mma_gemm_body(g_hrhi, g_hrlo, g_w2hi, g_w2lo, g_h2, NNODES, K2); }

// ---------------------------------------------------------------------------
// edge_index access (int64 per spec; tolerate int32 via runtime detection)
// ---------------------------------------------------------------------------
__device__ __forceinline__ int edge_idx(const void* ei, int half, int e) {
    if (g_is64) return (int)((const long long*)ei)[(size_t)half * NEDGES + e];
    return ((const int*)ei)[(size_t)half * NEDGES + e];
}

// ---------------------------------------------------------------------------
// CSR build: zero+detect -> count -> scan(+dinv) -> fill
// ---------------------------------------------------------------------------
__global__ void k_zero_detect(const long long* __restrict__ ei) {
    int i = blockIdx.x * blockDim.x + threadIdx.x;
    if (i < NNODES) g_ideg[i] = 0;
    if (blockIdx.x == 0 && threadIdx.x == 0) {
        int is64 = 1;
        for (int q = 0; q < 256; q++) {
            long long v = ei[q];
            if (v < 0 || v >= NNODES) { is64 = 0; break; }
        }
        g_is64 = is64;
    }
}

__global__ void k_count(const void* __restrict__ ei) {
    int e = blockIdx.x * blockDim.x + threadIdx.x;
    if (e < NEDGES) atomicAdd(&g_ideg[edge_idx(ei, 1, e)], 1);
}

#define SCAN_T 1024
#define SCAN_C ((NNODES + SCAN_T - 1) / SCAN_T)
__global__ void __launch_bounds__(SCAN_T)
k_scan() {
    __shared__ int part[SCAN_T];
    const int t = threadIdx.x;
    const int start = t * SCAN_C;
    const int end   = min(start + SCAN_C, NNODES);
    int s = 0;
    for (int i = start; i < end; i++) s += g_ideg[i];
    part[t] = s;
    __syncthreads();
    for (int off = 1; off < SCAN_T; off <<= 1) {
        int v = (t >= off) ? part[t - off] : 0;
        __syncthreads();
        part[t] += v;
        __syncthreads();
    }
    int run = part[t] - s;
    for (int i = start; i < end; i++) {
        int d = g_ideg[i];
        g_rowptr[i] = run;
        g_cursor[i] = run;
        g_dinv[i]   = rsqrtf(1.0f + (float)d);
        run += d;
    }
    if (t == SCAN_T - 1) g_rowptr[NNODES] = part[SCAN_T - 1];
}

__global__ void k_fill(const void* __restrict__ ei) {
    int e = blockIdx.x * blockDim.x + threadIdx.x;
    if (e >= NEDGES) return;
    int s = edge_idx(ei, 0, e);
    int d = edge_idx(ei, 1, e);
    int pos = atomicAdd(&g_cursor[d], 1);
    g_esrc[pos] = s;
}

// ---------------------------------------------------------------------------
// Gather aggregation: one warp per node.
// ---------------------------------------------------------------------------
__device__ __forceinline__ void gather_acc(
    const float* __restrict__ h, const float* __restrict__ bias,
    int node, int lane, float4& a0, float4& a1)
{
    const float dv = g_dinv[node];
    const float* hd = h + (size_t)node * CH;
    a0 = *(const float4*)&hd[lane * 4];
    a1 = *(const float4*)&hd[128 + lane * 4];
    const float sv = dv * dv;
    a0.x *= sv; a0.y *= sv; a0.z *= sv; a0.w *= sv;
    a1.x *= sv; a1.y *= sv; a1.z *= sv; a1.w *= sv;

    const int p0 = g_rowptr[node];
    const int p1 = g_rowptr[node + 1];
    for (int p = p0; p < p1; p++) {
        int s = g_esrc[p];
        float w = g_dinv[s] * dv;
        const float* hs = h + (size_t)s * CH;
        float4 v0 = *(const float4*)&hs[lane * 4];
        float4 v1 = *(const float4*)&hs[128 + lane * 4];
        a0.x = fmaf(v0.x, w, a0.x); a0.y = fmaf(v0.y, w, a0.y);
        a0.z = fmaf(v0.z, w, a0.z); a0.w = fmaf(v0.w, w, a0.w);
        a1.x = fmaf(v1.x, w, a1.x); a1.y = fmaf(v1.y, w, a1.y);
        a1.z = fmaf(v1.z, w, a1.z); a1.w = fmaf(v1.w, w, a1.w);
    }

    const float4 b0 = *(const float4*)&bias[lane * 4];
    const float4 b1 = *(const float4*)&bias[128 + lane * 4];
    a0.x += b0.x; a0.y += b0.y; a0.z += b0.z; a0.w += b0.w;
    a1.x += b1.x; a1.y += b1.y; a1.z += b1.z; a1.w += b1.w;
}

// layer 1: relu then emit bf16 hi/lo split directly (GEMM2 input)
__global__ void __launch_bounds__(256)
k_gather1(const float* __restrict__ b1)
{
    const int wid  = threadIdx.x >> 5;
    const int lane = threadIdx.x & 31;
    const int node = blockIdx.x * 8 + wid;
    if (node >= NNODES) return;
    float4 a0, a1;
    gather_acc(g_h1, b1, node, lane, a0, a1);
    a0.x = fmaxf(a0.x, 0.f); a0.y = fmaxf(a0.y, 0.f);
    a0.z = fmaxf(a0.z, 0.f); a0.w = fmaxf(a0.w, 0.f);
    a1.x = fmaxf(a1.x, 0.f); a1.y = fmaxf(a1.y, 0.f);
    a1.z = fmaxf(a1.z, 0.f); a1.w = fmaxf(a1.w, 0.f);

    uint32_t h0, l0, h1, l1;
    size_t bix = (size_t)node * 128 + lane * 2;
    bsplit2(a0.x, a0.y, h0, l0); bsplit2(a0.z, a0.w, h1, l1);
    *(uint2*)&g_hrhi[bix] = make_uint2(h0, h1);
    *(uint2*)&g_hrlo[bix] = make_uint2(l0, l1);
    bsplit2(a1.x, a1.y, h0, l0); bsplit2(a1.z, a1.w, h1, l1);
    *(uint2*)&g_hrhi[bix + 64] = make_uint2(h0, h1);
    *(uint2*)&g_hrlo[bix + 64] = make_uint2(l0, l1);
}

// layer 2: plain output
__global__ void __launch_bounds__(256)
k_gather2(const float* __restrict__ b2, float* __restrict__ out)
{
    const int wid  = threadIdx.x >> 5;
    const int lane = threadIdx.x & 31;
    const int node = blockIdx.x * 8 + wid;
    if (node >= NNODES) return;
    float4 a0, a1;
    gather_acc(g_h2, b2, node, lane, a0, a1);
    float* od = out + (size_t)node * CH;
    *(float4*)&od[lane * 4]       = a0;
    *(float4*)&od[128 + lane * 4] = a1;
}

// ---------------------------------------------------------------------------
// Launch
// ---------------------------------------------------------------------------
extern "C" void kernel_launch(void* const* d_in, const int* in_sizes, int n_in,
                              void* d_out, int out_size)
{
    const float* x   = (const float*)d_in[0];
    const void*  ei  = d_in[1];
    const float* W1  = (const float*)d_in[2];
    const float* b1  = (const float*)d_in[3];
    const float* W2  = (const float*)d_in[4];
    const float* b2  = (const float*)d_in[5];
    float*       out = (float*)d_out;

    static cudaStream_t s2 = nullptr;
    static cudaEvent_t  e0 = nullptr, e1 = nullptr;
    if (!s2) {
        cudaFuncSetAttribute(k_mmagemm1, cudaFuncAttributeMaxDynamicSharedMemorySize, GEMM_SMEM);
        cudaFuncSetAttribute(k_mmagemm2, cudaFuncAttributeMaxDynamicSharedMemorySize, GEMM_SMEM);
        cudaStreamCreateWithFlags(&s2, cudaStreamNonBlocking);
        cudaEventCreateWithFlags(&e0, cudaEventDisableTiming);
        cudaEventCreateWithFlags(&e1, cudaEventDisableTiming);
    }

    const int NTH = 256;
    const int nblk_nodes  = (NNODES + NTH - 1) / NTH;
    const int nblk_edges  = (NEDGES + NTH - 1) / NTH;
    const int nblk_gather = (NNODES + 7) / 8;
    const int nblk_conv   = (CONV_TOTAL + NTH - 1) / NTH;

    const int gemm_grid = (NNODES + 127) / 128;   // 391

    // fork: CSR chain on s2 (only gather1 depends on it)
    cudaEventRecord(e0, 0);
    cudaStreamWaitEvent(s2, e0, 0);
    k_zero_detect<<<nblk_nodes, NTH, 0, s2>>>((const long long*)ei);
    k_count<<<nblk_edges, NTH, 0, s2>>>(ei);
    k_scan<<<1, SCAN_T, 0, s2>>>();
    k_fill<<<nblk_edges, NTH, 0, s2>>>(ei);
    cudaEventRecord(e1, s2);

    // main: one conversion kernel (x + W1 + W2), then GEMM1
    k_conv_all<<<nblk_conv, NTH>>>(x, W1, W2);
    k_mmagemm1<<<gemm_grid, GEMM_NTH, GEMM_SMEM>>>();

    // join: gather1 needs CSR + dinv
    cudaStreamWaitEvent(0, e1, 0);
    k_gather1<<<nblk_gather, NTH>>>(b1);

    // layer 2
    k_mmagemm2<<<gemm_grid, GEMM_NTH, GEMM_SMEM>>>();
    k_gather2<<<nblk_gather, NTH>>>(b2, out);
}